// round 6
// baseline (speedup 1.0000x reference)
#include <cuda_runtime.h>
#include <cuda_bf16.h>
#include <cstdint>
#include <cstddef>

// Problem constants (B=4, S=4096, H=16, D=64)
#define BSZ 4
#define SEQ 4096
#define NH 16
#define HD 64
#define CK 128
#define NC 32
#define BH 64
#define ROWSTRIDE 1024

// Per-chunk KV outer products -> exclusive prefix (in place). 32 MB.
__device__ float g_kv[(size_t)BH * NC * HD * HD];

// ---------------------------------------------------------------------------
// PTX helpers (base sm_100-safe)
// ---------------------------------------------------------------------------
__device__ __forceinline__ uint32_t smem_u32(const void* p) {
    uint32_t a;
    asm("{ .reg .u64 t; cvta.to.shared.u64 t, %1; cvt.u32.u64 %0, t; }"
        : "=r"(a) : "l"(p));
    return a;
}
__device__ __forceinline__ void ldm4(uint32_t* r, uint32_t addr) {
    asm volatile("ldmatrix.sync.aligned.m8n8.x4.shared.b16 {%0,%1,%2,%3}, [%4];"
                 : "=r"(r[0]), "=r"(r[1]), "=r"(r[2]), "=r"(r[3]) : "r"(addr));
}
__device__ __forceinline__ void ldm4t(uint32_t* r, uint32_t addr) {
    asm volatile("ldmatrix.sync.aligned.m8n8.x4.trans.shared.b16 {%0,%1,%2,%3}, [%4];"
                 : "=r"(r[0]), "=r"(r[1]), "=r"(r[2]), "=r"(r[3]) : "r"(addr));
}
__device__ __forceinline__ void mma16816(float* c, const uint32_t* a, const uint32_t* b) {
    asm volatile(
        "mma.sync.aligned.m16n8k16.row.col.f32.bf16.bf16.f32 "
        "{%0,%1,%2,%3}, {%4,%5,%6,%7}, {%8,%9}, {%0,%1,%2,%3};"
        : "+f"(c[0]), "+f"(c[1]), "+f"(c[2]), "+f"(c[3])
        : "r"(a[0]), "r"(a[1]), "r"(a[2]), "r"(a[3]), "r"(b[0]), "r"(b[1]));
}

// swizzles: 128B rows ([*][64] bf16) and 256B rows ([*][128] bf16)
__device__ __forceinline__ uint32_t sw128(uint32_t x) { return x ^ ((x >> 3) & 0x70); }
__device__ __forceinline__ uint32_t sw256(uint32_t x) { return x ^ ((x >> 4) & 0x70); }

// split fp32 -> (hi, lo) bf16
__device__ __forceinline__ void split1(float x, __nv_bfloat16& h, __nv_bfloat16& l) {
    h = __float2bfloat16(x);
    l = __float2bfloat16(x - __bfloat162float(h));
}
__device__ __forceinline__ void split2(float x0, float x1, uint32_t& hi, uint32_t& lo) {
    __nv_bfloat16 h0, l0, h1, l1;
    split1(x0, h0, l0);
    split1(x1, h1, l1);
    hi = (uint32_t)__bfloat16_as_ushort(h0) | ((uint32_t)__bfloat16_as_ushort(h1) << 16);
    lo = (uint32_t)__bfloat16_as_ushort(l0) | ((uint32_t)__bfloat16_as_ushort(l1) << 16);
}

// ---------------------------------------------------------------------------
// Kernel 1: per-chunk KV_n[d][e] = sum_j k[j][d] * v[j][e]   (unchanged)
// ---------------------------------------------------------------------------
#define KV_KH 0
#define KV_KL 16384
#define KV_VH 32768
#define KV_VL 49152
#define KV_SMEM 65536

__global__ __launch_bounds__(512, 2) void kv_chunk_kernel(
    const float* __restrict__ kg, const float* __restrict__ vg) {
    extern __shared__ char sm[];
    const uint32_t smb = smem_u32(sm);

    const int tid = threadIdx.x, wid = tid >> 5, lane = tid & 31;
    const int blk = blockIdx.x;
    const int n = blk & (NC - 1), bh = blk >> 5;
    const int h = bh & (NH - 1), b = bh >> 4;
    const size_t base = ((size_t)b * SEQ + (size_t)n * CK) * ROWSTRIDE + (size_t)h * HD;

#pragma unroll
    for (int p = tid; p < 4096; p += 512) {
        const int j = p >> 5, dp = p & 31;
        const size_t g = base + (size_t)j * ROWSTRIDE + 2 * dp;
        float2 xk = *(const float2*)(kg + g);
        float2 xv = *(const float2*)(vg + g);
        uint32_t kh, kl, vh, vl;
        split2(xk.x, xk.y, kh, kl);
        split2(xv.x, xv.y, vh, vl);
        const uint32_t off = sw128((uint32_t)(j * 128 + dp * 4));
        *(uint32_t*)(sm + KV_KH + off) = kh;
        *(uint32_t*)(sm + KV_KL + off) = kl;
        *(uint32_t*)(sm + KV_VH + off) = vh;
        *(uint32_t*)(sm + KV_VL + off) = vl;
    }
    __syncthreads();

    const int wy = wid >> 2;          // d block of 16
    const int wx = wid & 3;           // e block of 16
    const int la7 = lane & 7;

    float acc[2][4];
#pragma unroll
    for (int f = 0; f < 2; f++)
#pragma unroll
        for (int c = 0; c < 4; c++) acc[f][c] = 0.f;

#pragma unroll 2
    for (int kb = 0; kb < 8; kb++) {
        const int k0 = kb * 16;
        uint32_t aH[4], aL[4];
        {
            const int row = k0 + ((lane >> 4) << 3) + la7;
            const int col = wy * 16 + ((lane >> 3) & 1) * 8;
            const uint32_t off = sw128((uint32_t)(row * 128 + col * 2));
            ldm4t(aH, smb + KV_KH + off);
            ldm4t(aL, smb + KV_KL + off);
        }
        uint32_t bH[4], bL[4];
        {
            const int row = k0 + ((lane >> 3) & 1) * 8 + la7;
            const int col = wx * 16 + ((lane >> 4) << 3);
            const uint32_t off = sw128((uint32_t)(row * 128 + col * 2));
            ldm4t(bH, smb + KV_VH + off);
            ldm4t(bL, smb + KV_VL + off);
        }
#pragma unroll
        for (int f = 0; f < 2; f++) {
            float* c = acc[f];
            mma16816(c, aH, &bH[2 * f]);
            mma16816(c, aH, &bL[2 * f]);
            mma16816(c, aL, &bH[2 * f]);
        }
    }

    {
        float* out = g_kv + ((size_t)bh * NC + n) * (HD * HD);
        const int gid = lane >> 2, t4 = lane & 3;
#pragma unroll
        for (int f = 0; f < 2; f++) {
            const int e0 = wx * 16 + f * 8 + 2 * t4;
            const int d0 = wy * 16 + gid;
            *(float2*)(out + d0 * HD + e0) = make_float2(acc[f][0], acc[f][1]);
            *(float2*)(out + (d0 + 8) * HD + e0) = make_float2(acc[f][2], acc[f][3]);
        }
    }
}

// ---------------------------------------------------------------------------
// Kernel 2: in-place exclusive prefix over chunk axis (unchanged)
// ---------------------------------------------------------------------------
__global__ __launch_bounds__(256, 1) void kv_prefix_kernel() {
    const int bh  = blockIdx.x >> 4;
    const int off = ((blockIdx.x & 15) << 8) + threadIdx.x;
    float* p = g_kv + (size_t)bh * NC * (HD * HD) + off;
    float run = 0.f;
#pragma unroll
    for (int n = 0; n < NC; n++) {
        const float t = p[(size_t)n * (HD * HD)];
        p[(size_t)n * (HD * HD)] = run;
        run += t;
    }
}

// ---------------------------------------------------------------------------
// Kernel 3: out kernel, half-chunk CTAs (64 i-rows each), 256 threads, 96 KB.
//   HALF=0: i in [0,64),  needs K/V rows [0,64)   -> S 64x64,  less work
//   HALF=1: i in [64,128), needs K/V rows [0,128) -> S 64x128
// smem: QH 0, QL 8K            ([64][64] K-major, SW128)   live all phases
//       KH 16K, KL 32K         ([<=128][64] K-major, SW128) dead after A
//       SH 16K, SL 32K         ([64][128], SW256) overlays K
//       VH 48K, VL 64K         ([<=128][64] natural [j][e], SW128)
//       KVH 80K, KVL 88K       ([64][64] natural [d][e], SW128)
// Warps: 8; wy=wid>>2 (i block 32), wx=wid&3 (S: j block JW / O: e block 16).
// ---------------------------------------------------------------------------
#define O_QH 0
#define O_QL 8192
#define O_KH 16384
#define O_KL 32768
#define O_SH 16384
#define O_SL 32768
#define O_VH 49152
#define O_VL 65536
#define O_KVH 81920
#define O_KVL 90112
#define O_SMEM 98304

template <int HALF>
__device__ __forceinline__ void out_body(
    char* sm, uint32_t smb,
    const float* __restrict__ qg, const float* __restrict__ kg,
    const float* __restrict__ vg, float* __restrict__ og,
    const float* __restrict__ kvsrc, size_t base) {
    constexpr int JMAX = 64 * (HALF + 1);   // K/V rows needed
    constexpr int JW   = JMAX / 4;          // j width per warp in phase A
    constexpr int G    = JW / 16;           // 16-col groups per warp (1 or 2)
    constexpr int KB1  = JMAX / 16;         // k-blocks in S·V
    const int i0 = HALF * 64;

    const int tid = threadIdx.x, wid = tid >> 5, lane = tid & 31;
    const size_t baseQ = base + (size_t)i0 * ROWSTRIDE;

    // ---- loads + split ----
#pragma unroll
    for (int p = tid; p < 2048; p += 256) {           // Q rows i0..i0+63
        const int i = p >> 5, dp = p & 31;
        float2 x = *(const float2*)(qg + baseQ + (size_t)i * ROWSTRIDE + 2 * dp);
        uint32_t hh, ll;
        split2(x.x, x.y, hh, ll);
        const uint32_t off = sw128((uint32_t)(i * 128 + dp * 4));
        *(uint32_t*)(sm + O_QH + off) = hh;
        *(uint32_t*)(sm + O_QL + off) = ll;
    }
#pragma unroll
    for (int p = tid; p < JMAX * 32; p += 256) {      // K,V rows 0..JMAX-1
        const int j = p >> 5, dp = p & 31;
        const size_t g = base + (size_t)j * ROWSTRIDE + 2 * dp;
        float2 xk = *(const float2*)(kg + g);
        float2 xv = *(const float2*)(vg + g);
        uint32_t hh, ll;
        const uint32_t off = sw128((uint32_t)(j * 128 + dp * 4));
        split2(xk.x, xk.y, hh, ll);
        *(uint32_t*)(sm + O_KH + off) = hh;
        *(uint32_t*)(sm + O_KL + off) = ll;
        split2(xv.x, xv.y, hh, ll);
        *(uint32_t*)(sm + O_VH + off) = hh;
        *(uint32_t*)(sm + O_VL + off) = ll;
    }
#pragma unroll
    for (int p = tid; p < 2048; p += 256) {           // KV_prev [64][64]
        const int d = p >> 5, ep = p & 31;
        float2 x = *(const float2*)(kvsrc + d * 64 + 2 * ep);
        uint32_t hh, ll;
        split2(x.x, x.y, hh, ll);
        const uint32_t off = sw128((uint32_t)(d * 128 + ep * 4));
        *(uint32_t*)(sm + O_KVH + off) = hh;
        *(uint32_t*)(sm + O_KVL + off) = ll;
    }
    __syncthreads();

    const int wy = wid >> 2;   // i block of 32 (local)
    const int wx = wid & 3;    // S: j block of JW / O: e block of 16
    const int la7 = lane & 7;
    const int la15 = lane & 15;

    // ---- phase A: S = Q K^T (3 split terms) ----
    float sacc[2][2 * G][4];
#pragma unroll
    for (int m = 0; m < 2; m++)
#pragma unroll
        for (int g = 0; g < 2 * G; g++)
#pragma unroll
            for (int c = 0; c < 4; c++) sacc[m][g][c] = 0.f;

#pragma unroll
    for (int kb = 0; kb < 4; kb++) {
        const int k0 = kb * 16;
        uint32_t aH[2][4], aL[2][4];
#pragma unroll
        for (int m = 0; m < 2; m++) {
            const int row = wy * 32 + m * 16 + la15;
            const int col = k0 + ((lane >> 4) << 3);
            const uint32_t off = sw128((uint32_t)(row * 128 + col * 2));
            ldm4(aH[m], smb + O_QH + off);
            ldm4(aL[m], smb + O_QL + off);
        }
        uint32_t bH[G][4], bL[G][4];
#pragma unroll
        for (int nb = 0; nb < G; nb++) {
            const int row = wx * JW + nb * 16 + ((lane >> 4) << 3) + la7;
            const int col = k0 + ((lane >> 3) & 1) * 8;
            const uint32_t off = sw128((uint32_t)(row * 128 + col * 2));
            ldm4(bH[nb], smb + O_KH + off);
            ldm4(bL[nb], smb + O_KL + off);
        }
#pragma unroll
        for (int m = 0; m < 2; m++)
#pragma unroll
            for (int nb = 0; nb < G; nb++)
#pragma unroll
                for (int f = 0; f < 2; f++) {
                    float* c = sacc[m][nb * 2 + f];
                    mma16816(c, aH[m], &bH[nb][2 * f]);
                    mma16816(c, aH[m], &bL[nb][2 * f]);
                    mma16816(c, aL[m], &bH[nb][2 * f]);
                }
    }
    __syncthreads();   // all reads of K done before S overlays it

    // ---- phase B: mask + split S -> SH/SL ([64][128], SW256) ----
    {
        const int gid = lane >> 2, t4 = lane & 3;
#pragma unroll
        for (int m = 0; m < 2; m++)
#pragma unroll
            for (int g = 0; g < 2 * G; g++) {
                const int j0 = wx * JW + g * 8 + 2 * t4;
#pragma unroll
                for (int hf = 0; hf < 2; hf++) {
                    const int iloc = wy * 32 + m * 16 + gid + hf * 8;
                    const int igl = i0 + iloc;
                    const float x0 = (j0     <= igl) ? sacc[m][g][2 * hf]     : 0.f;
                    const float x1 = (j0 + 1 <= igl) ? sacc[m][g][2 * hf + 1] : 0.f;
                    uint32_t hh, ll;
                    split2(x0, x1, hh, ll);
                    const uint32_t off = sw256((uint32_t)(iloc * 256 + j0 * 2));
                    *(uint32_t*)(sm + O_SH + off) = hh;
                    *(uint32_t*)(sm + O_SL + off) = ll;
                }
            }
    }
    __syncthreads();

    // ---- phase C: O = S·V + Q·KV_prev (3 split terms each) ----
    float oacc[2][2][4];
#pragma unroll
    for (int m = 0; m < 2; m++)
#pragma unroll
        for (int f = 0; f < 2; f++)
#pragma unroll
            for (int c = 0; c < 4; c++) oacc[m][f][c] = 0.f;

#pragma unroll
    for (int kb = 0; kb < KB1; kb++) {               // A = S, B = V (trans)
        const int k0 = kb * 16;
        uint32_t aH[2][4], aL[2][4];
#pragma unroll
        for (int m = 0; m < 2; m++) {
            const int row = wy * 32 + m * 16 + la15;
            const int col = k0 + ((lane >> 4) << 3);
            const uint32_t off = sw256((uint32_t)(row * 256 + col * 2));
            ldm4(aH[m], smb + O_SH + off);
            ldm4(aL[m], smb + O_SL + off);
        }
        uint32_t bH[4], bL[4];
        {
            const int row = k0 + ((lane >> 3) & 1) * 8 + la7;
            const int col = wx * 16 + ((lane >> 4) << 3);
            const uint32_t off = sw128((uint32_t)(row * 128 + col * 2));
            ldm4t(bH, smb + O_VH + off);
            ldm4t(bL, smb + O_VL + off);
        }
#pragma unroll
        for (int m = 0; m < 2; m++)
#pragma unroll
            for (int f = 0; f < 2; f++) {
                float* c = oacc[m][f];
                mma16816(c, aH[m], &bH[2 * f]);
                mma16816(c, aH[m], &bL[2 * f]);
                mma16816(c, aL[m], &bH[2 * f]);
            }
    }
#pragma unroll
    for (int kb = 0; kb < 4; kb++) {                 // A = Q, B = KV (trans)
        const int k0 = kb * 16;
        uint32_t aH[2][4], aL[2][4];
#pragma unroll
        for (int m = 0; m < 2; m++) {
            const int row = wy * 32 + m * 16 + la15;
            const int col = k0 + ((lane >> 4) << 3);
            const uint32_t off = sw128((uint32_t)(row * 128 + col * 2));
            ldm4(aH[m], smb + O_QH + off);
            ldm4(aL[m], smb + O_QL + off);
        }
        uint32_t bH[4], bL[4];
        {
            const int row = k0 + ((lane >> 3) & 1) * 8 + la7;
            const int col = wx * 16 + ((lane >> 4) << 3);
            const uint32_t off = sw128((uint32_t)(row * 128 + col * 2));
            ldm4t(bH, smb + O_KVH + off);
            ldm4t(bL, smb + O_KVL + off);
        }
#pragma unroll
        for (int m = 0; m < 2; m++)
#pragma unroll
            for (int f = 0; f < 2; f++) {
                float* c = oacc[m][f];
                mma16816(c, aH[m], &bH[2 * f]);
                mma16816(c, aH[m], &bL[2 * f]);
                mma16816(c, aL[m], &bH[2 * f]);
            }
    }

    // ---- epilogue ----
    {
        const int gid = lane >> 2, t4 = lane & 3;
#pragma unroll
        for (int m = 0; m < 2; m++)
#pragma unroll
            for (int f = 0; f < 2; f++) {
                const int e0 = wx * 16 + f * 8 + 2 * t4;
                const int il = wy * 32 + m * 16 + gid;
                *(float2*)(og + baseQ + (size_t)il * ROWSTRIDE + e0) =
                    make_float2(oacc[m][f][0], oacc[m][f][1]);
                *(float2*)(og + baseQ + (size_t)(il + 8) * ROWSTRIDE + e0) =
                    make_float2(oacc[m][f][2], oacc[m][f][3]);
            }
    }
}

__global__ __launch_bounds__(256, 2) void out_mma_kernel(
    const float* __restrict__ qg, const float* __restrict__ kg,
    const float* __restrict__ vg, float* __restrict__ og) {
    extern __shared__ char sm[];
    const uint32_t smb = smem_u32(sm);

    const int blk = blockIdx.x;
    const int half = blk & 1;
    const int cidx = blk >> 1;
    const int n = cidx & (NC - 1), bh = cidx >> 5;
    const int h = bh & (NH - 1), b = bh >> 4;
    const size_t base = ((size_t)b * SEQ + (size_t)n * CK) * ROWSTRIDE + (size_t)h * HD;
    const float* kvsrc = g_kv + ((size_t)bh * NC + n) * (HD * HD);

    if (half) out_body<1>(sm, smb, qg, kg, vg, og, kvsrc, base);
    else      out_body<0>(sm, smb, qg, kg, vg, og, kvsrc, base);
}

// ---------------------------------------------------------------------------
// kernel_launch
// ---------------------------------------------------------------------------
extern "C" void kernel_launch(void* const* d_in, const int* in_sizes, int n_in,
                              void* d_out, int out_size) {
    (void)in_sizes; (void)n_in; (void)out_size;
    const float* q = (const float*)d_in[0];
    const float* k = (const float*)d_in[1];
    const float* v = (const float*)d_in[2];
    float* out = (float*)d_out;

    cudaFuncSetAttribute(kv_chunk_kernel, cudaFuncAttributeMaxDynamicSharedMemorySize,
                         KV_SMEM);
    kv_chunk_kernel<<<BH * NC, 512, KV_SMEM>>>(k, v);
    kv_prefix_kernel<<<BH * 16, 256>>>();

    cudaFuncSetAttribute(out_mma_kernel, cudaFuncAttributeMaxDynamicSharedMemorySize,
                         O_SMEM);
    out_mma_kernel<<<BH * NC * 2, 256, O_SMEM>>>(q, k, v, out);
}

// round 7
// speedup vs baseline: 1.3150x; 1.3150x over previous
#include <cuda_runtime.h>
#include <cuda_bf16.h>
#include <cstdint>
#include <cstddef>

// Problem constants (B=4, S=4096, H=16, D=64)
#define BSZ 4
#define SEQ 4096
#define NH 16
#define HD 64
#define CK 128
#define NC 32
#define BH 64
#define ROWSTRIDE 1024

// Per-chunk KV outer products -> exclusive prefix (in place). 32 MB.
__device__ float g_kv[(size_t)BH * NC * HD * HD];

// ---------------------------------------------------------------------------
// PTX helpers (base sm_100-safe)
// ---------------------------------------------------------------------------
__device__ __forceinline__ uint32_t smem_u32(const void* p) {
    uint32_t a;
    asm("{ .reg .u64 t; cvta.to.shared.u64 t, %1; cvt.u32.u64 %0, t; }"
        : "=r"(a) : "l"(p));
    return a;
}
__device__ __forceinline__ void ldm4(uint32_t* r, uint32_t addr) {
    asm volatile("ldmatrix.sync.aligned.m8n8.x4.shared.b16 {%0,%1,%2,%3}, [%4];"
                 : "=r"(r[0]), "=r"(r[1]), "=r"(r[2]), "=r"(r[3]) : "r"(addr));
}
__device__ __forceinline__ void ldm4t(uint32_t* r, uint32_t addr) {
    asm volatile("ldmatrix.sync.aligned.m8n8.x4.trans.shared.b16 {%0,%1,%2,%3}, [%4];"
                 : "=r"(r[0]), "=r"(r[1]), "=r"(r[2]), "=r"(r[3]) : "r"(addr));
}
__device__ __forceinline__ void mma16816(float* c, const uint32_t* a, const uint32_t* b) {
    asm volatile(
        "mma.sync.aligned.m16n8k16.row.col.f32.bf16.bf16.f32 "
        "{%0,%1,%2,%3}, {%4,%5,%6,%7}, {%8,%9}, {%0,%1,%2,%3};"
        : "+f"(c[0]), "+f"(c[1]), "+f"(c[2]), "+f"(c[3])
        : "r"(a[0]), "r"(a[1]), "r"(a[2]), "r"(a[3]), "r"(b[0]), "r"(b[1]));
}

// swizzle for 128B rows ([*][64] bf16)
__device__ __forceinline__ uint32_t sw128(uint32_t x) { return x ^ ((x >> 3) & 0x70); }

// split fp32 -> (hi, lo) bf16
__device__ __forceinline__ void split1(float x, __nv_bfloat16& h, __nv_bfloat16& l) {
    h = __float2bfloat16(x);
    l = __float2bfloat16(x - __bfloat162float(h));
}
__device__ __forceinline__ void split2(float x0, float x1, uint32_t& hi, uint32_t& lo) {
    __nv_bfloat16 h0, l0, h1, l1;
    split1(x0, h0, l0);
    split1(x1, h1, l1);
    hi = (uint32_t)__bfloat16_as_ushort(h0) | ((uint32_t)__bfloat16_as_ushort(h1) << 16);
    lo = (uint32_t)__bfloat16_as_ushort(l0) | ((uint32_t)__bfloat16_as_ushort(l1) << 16);
}

// ---------------------------------------------------------------------------
// Kernel 1: per-chunk KV_n[d][e] = sum_j k[j][d] * v[j][e]   (unchanged, at
// its memory floor)
// ---------------------------------------------------------------------------
#define KV_KH 0
#define KV_KL 16384
#define KV_VH 32768
#define KV_VL 49152
#define KV_SMEM 65536

__global__ __launch_bounds__(512, 2) void kv_chunk_kernel(
    const float* __restrict__ kg, const float* __restrict__ vg) {
    extern __shared__ char sm[];
    const uint32_t smb = smem_u32(sm);

    const int tid = threadIdx.x, wid = tid >> 5, lane = tid & 31;
    const int blk = blockIdx.x;
    const int n = blk & (NC - 1), bh = blk >> 5;
    const int h = bh & (NH - 1), b = bh >> 4;
    const size_t base = ((size_t)b * SEQ + (size_t)n * CK) * ROWSTRIDE + (size_t)h * HD;

#pragma unroll
    for (int p = tid; p < 4096; p += 512) {
        const int j = p >> 5, dp = p & 31;
        const size_t g = base + (size_t)j * ROWSTRIDE + 2 * dp;
        float2 xk = *(const float2*)(kg + g);
        float2 xv = *(const float2*)(vg + g);
        uint32_t kh, kl, vh, vl;
        split2(xk.x, xk.y, kh, kl);
        split2(xv.x, xv.y, vh, vl);
        const uint32_t off = sw128((uint32_t)(j * 128 + dp * 4));
        *(uint32_t*)(sm + KV_KH + off) = kh;
        *(uint32_t*)(sm + KV_KL + off) = kl;
        *(uint32_t*)(sm + KV_VH + off) = vh;
        *(uint32_t*)(sm + KV_VL + off) = vl;
    }
    __syncthreads();

    const int wy = wid >> 2;          // d block of 16
    const int wx = wid & 3;           // e block of 16
    const int la7 = lane & 7;

    float acc[2][4];
#pragma unroll
    for (int f = 0; f < 2; f++)
#pragma unroll
        for (int c = 0; c < 4; c++) acc[f][c] = 0.f;

#pragma unroll 2
    for (int kb = 0; kb < 8; kb++) {
        const int k0 = kb * 16;
        uint32_t aH[4], aL[4];
        {
            const int row = k0 + ((lane >> 4) << 3) + la7;
            const int col = wy * 16 + ((lane >> 3) & 1) * 8;
            const uint32_t off = sw128((uint32_t)(row * 128 + col * 2));
            ldm4t(aH, smb + KV_KH + off);
            ldm4t(aL, smb + KV_KL + off);
        }
        uint32_t bH[4], bL[4];
        {
            const int row = k0 + ((lane >> 3) & 1) * 8 + la7;
            const int col = wx * 16 + ((lane >> 4) << 3);
            const uint32_t off = sw128((uint32_t)(row * 128 + col * 2));
            ldm4t(bH, smb + KV_VH + off);
            ldm4t(bL, smb + KV_VL + off);
        }
#pragma unroll
        for (int f = 0; f < 2; f++) {
            float* c = acc[f];
            mma16816(c, aH, &bH[2 * f]);
            mma16816(c, aH, &bL[2 * f]);
            mma16816(c, aL, &bH[2 * f]);
        }
    }

    {
        float* out = g_kv + ((size_t)bh * NC + n) * (HD * HD);
        const int gid = lane >> 2, t4 = lane & 3;
#pragma unroll
        for (int f = 0; f < 2; f++) {
            const int e0 = wx * 16 + f * 8 + 2 * t4;
            const int d0 = wy * 16 + gid;
            *(float2*)(out + d0 * HD + e0) = make_float2(acc[f][0], acc[f][1]);
            *(float2*)(out + (d0 + 8) * HD + e0) = make_float2(acc[f][2], acc[f][3]);
        }
    }
}

// ---------------------------------------------------------------------------
// Kernel 2: in-place exclusive prefix over chunk axis (unchanged)
// ---------------------------------------------------------------------------
__global__ __launch_bounds__(256, 1) void kv_prefix_kernel() {
    const int bh  = blockIdx.x >> 4;
    const int off = ((blockIdx.x & 15) << 8) + threadIdx.x;
    float* p = g_kv + (size_t)bh * NC * (HD * HD) + off;
    float run = 0.f;
#pragma unroll
    for (int n = 0; n < NC; n++) {
        const float t = p[(size_t)n * (HD * HD)];
        p[(size_t)n * (HD * HD)] = run;
        run += t;
    }
}

// ---------------------------------------------------------------------------
// Kernel 3: out kernel, register-resident S (FA2 style), 256 thr, 112 KB,
// 2 CTAs/SM.
//   O = tril(Q K^T) V + Q KV_prev  per 128-row chunk.
// smem: QH 0, QL 16K       ([128][64] K-major, SW128)
//       KH 32K, KL 48K     ([128][64] K-major, SW128)
//       VH 64K, VL 80K     ([128][64] natural [j][e], SW128)
//       KVH 96K, KVL 104K  ([64][64] natural [d][e], SW128)
// 8 warps, each owns 16 i-rows (i0w = wid*16), all 64 e-cols.
// Two j-half passes; S never touches smem: sacc -> mask -> split ->
// A-fragments in registers -> S·V. Causal block-skip at warp granularity.
// ---------------------------------------------------------------------------
#define O_QH 0
#define O_QL 16384
#define O_KH 32768
#define O_KL 49152
#define O_VH 65536
#define O_VL 81920
#define O_KVH 98304
#define O_KVL 106496
#define O_SMEM 114688

__global__ __launch_bounds__(256, 2) void out_mma_kernel(
    const float* __restrict__ qg, const float* __restrict__ kg,
    const float* __restrict__ vg, float* __restrict__ og) {
    extern __shared__ char sm[];
    const uint32_t smb = smem_u32(sm);

    const int tid = threadIdx.x, wid = tid >> 5, lane = tid & 31;
    const int blk = blockIdx.x;
    const int n = blk & (NC - 1), bh = blk >> 5;
    const int h = bh & (NH - 1), b = bh >> 4;
    const size_t base = ((size_t)b * SEQ + (size_t)n * CK) * ROWSTRIDE + (size_t)h * HD;

    // ---- load + split: Q, K, V ----
#pragma unroll
    for (int p = tid; p < 4096; p += 256) {
        const int i = p >> 5, dp = p & 31;
        const size_t g = base + (size_t)i * ROWSTRIDE + 2 * dp;
        float2 xq = *(const float2*)(qg + g);
        float2 xk = *(const float2*)(kg + g);
        float2 xv = *(const float2*)(vg + g);
        uint32_t hh, ll;
        const uint32_t off = sw128((uint32_t)(i * 128 + dp * 4));
        split2(xq.x, xq.y, hh, ll);
        *(uint32_t*)(sm + O_QH + off) = hh;
        *(uint32_t*)(sm + O_QL + off) = ll;
        split2(xk.x, xk.y, hh, ll);
        *(uint32_t*)(sm + O_KH + off) = hh;
        *(uint32_t*)(sm + O_KL + off) = ll;
        split2(xv.x, xv.y, hh, ll);
        *(uint32_t*)(sm + O_VH + off) = hh;
        *(uint32_t*)(sm + O_VL + off) = ll;
    }
    // KV_prev [64][64]
    {
        const float* kvsrc = g_kv + ((size_t)bh * NC + n) * (HD * HD);
#pragma unroll
        for (int p = tid; p < 2048; p += 256) {
            const int d = p >> 5, ep = p & 31;
            float2 x = *(const float2*)(kvsrc + d * 64 + 2 * ep);
            uint32_t hh, ll;
            split2(x.x, x.y, hh, ll);
            const uint32_t off = sw128((uint32_t)(d * 128 + ep * 4));
            *(uint32_t*)(sm + O_KVH + off) = hh;
            *(uint32_t*)(sm + O_KVL + off) = ll;
        }
    }
    __syncthreads();

    const int i0w = wid * 16;            // warp's first i-row
    const int la7 = lane & 7;
    const int la15 = lane & 15;
    const int gid = lane >> 2, t4 = lane & 3;
    const int iMax = i0w + 15;

    float oacc[8][4];                    // e n-blocks 0..7 (e = 8nb..)
#pragma unroll
    for (int nb = 0; nb < 8; nb++)
#pragma unroll
        for (int c = 0; c < 4; c++) oacc[nb][c] = 0.f;

    // ---- two j-half passes: S (registers) then S·V ----
#pragma unroll
    for (int jh = 0; jh < 2; jh++) {
        const int jbase = jh * 64;
        if (jbase <= iMax) {
            // S = Q K^T for j in [jbase, jbase+64)
            float sacc[8][4];
#pragma unroll
            for (int nb = 0; nb < 8; nb++)
#pragma unroll
                for (int c = 0; c < 4; c++) sacc[nb][c] = 0.f;

#pragma unroll
            for (int kb = 0; kb < 4; kb++) {
                const int k0 = kb * 16;
                uint32_t qh4[4], ql4[4];
                {
                    const int row = i0w + la15;
                    const int col = k0 + ((lane >> 4) << 3);
                    const uint32_t off = sw128((uint32_t)(row * 128 + col * 2));
                    ldm4(qh4, smb + O_QH + off);
                    ldm4(ql4, smb + O_QL + off);
                }
#pragma unroll
                for (int pb = 0; pb < 4; pb++) {
                    if (jbase + pb * 16 <= iMax) {
                        uint32_t bH4[4], bL4[4];
                        const int row = jbase + pb * 16 + ((lane >> 4) << 3) + la7;
                        const int col = k0 + ((lane >> 3) & 1) * 8;
                        const uint32_t off = sw128((uint32_t)(row * 128 + col * 2));
                        ldm4(bH4, smb + O_KH + off);
                        ldm4(bL4, smb + O_KL + off);
#pragma unroll
                        for (int f = 0; f < 2; f++) {
                            float* c = sacc[pb * 2 + f];
                            mma16816(c, qh4, &bH4[2 * f]);
                            mma16816(c, qh4, &bL4[2 * f]);
                            mma16816(c, ql4, &bH4[2 * f]);
                        }
                    }
                }
            }

            // mask + split in registers -> A fragments (FA2 layout match)
            uint32_t aSH[4][4], aSL[4][4];
#pragma unroll
            for (int kb = 0; kb < 4; kb++)
#pragma unroll
                for (int r = 0; r < 4; r++) { aSH[kb][r] = 0u; aSL[kb][r] = 0u; }

#pragma unroll
            for (int nb = 0; nb < 8; nb++) {
                const int jb = jbase + nb * 8;
                if (jb <= iMax) {
                    const int j0 = jb + 2 * t4;
                    const int iLo = i0w + gid, iHi = iLo + 8;
                    const float x0 = (j0     <= iLo) ? sacc[nb][0] : 0.f;
                    const float x1 = (j0 + 1 <= iLo) ? sacc[nb][1] : 0.f;
                    const float x2 = (j0     <= iHi) ? sacc[nb][2] : 0.f;
                    const float x3 = (j0 + 1 <= iHi) ? sacc[nb][3] : 0.f;
                    uint32_t hi01, lo01, hi23, lo23;
                    split2(x0, x1, hi01, lo01);
                    split2(x2, x3, hi23, lo23);
                    const int kb = nb >> 1, sl = (nb & 1) * 2;
                    aSH[kb][sl] = hi01;  aSH[kb][sl + 1] = hi23;
                    aSL[kb][sl] = lo01;  aSL[kb][sl + 1] = lo23;
                }
            }

            // S·V over this j-half: B = V rows [jbase+16kb ...] (trans)
#pragma unroll
            for (int kb = 0; kb < 4; kb++) {
                if (jbase + kb * 16 <= iMax) {
                    const int rowv = jbase + kb * 16 + ((lane >> 3) & 1) * 8 + la7;
#pragma unroll
                    for (int pe = 0; pe < 4; pe++) {
                        uint32_t vH4[4], vL4[4];
                        const int col = pe * 16 + ((lane >> 4) << 3);
                        const uint32_t off = sw128((uint32_t)(rowv * 128 + col * 2));
                        ldm4t(vH4, smb + O_VH + off);
                        ldm4t(vL4, smb + O_VL + off);
#pragma unroll
                        for (int f = 0; f < 2; f++) {
                            float* c = oacc[pe * 2 + f];
                            mma16816(c, aSH[kb], &vH4[2 * f]);
                            mma16816(c, aSH[kb], &vL4[2 * f]);
                            mma16816(c, aSL[kb], &vH4[2 * f]);
                        }
                    }
                }
            }
        }
    }

    // ---- O += Q KV_prev ----
#pragma unroll
    for (int kb = 0; kb < 4; kb++) {
        const int k0 = kb * 16;
        uint32_t qh4[4], ql4[4];
        {
            const int row = i0w + la15;
            const int col = k0 + ((lane >> 4) << 3);
            const uint32_t off = sw128((uint32_t)(row * 128 + col * 2));
            ldm4(qh4, smb + O_QH + off);
            ldm4(ql4, smb + O_QL + off);
        }
        const int rowkv = k0 + ((lane >> 3) & 1) * 8 + la7;
#pragma unroll
        for (int pe = 0; pe < 4; pe++) {
            uint32_t bH4[4], bL4[4];
            const int col = pe * 16 + ((lane >> 4) << 3);
            const uint32_t off = sw128((uint32_t)(rowkv * 128 + col * 2));
            ldm4t(bH4, smb + O_KVH + off);
            ldm4t(bL4, smb + O_KVL + off);
#pragma unroll
            for (int f = 0; f < 2; f++) {
                float* c = oacc[pe * 2 + f];
                mma16816(c, qh4, &bH4[2 * f]);
                mma16816(c, qh4, &bL4[2 * f]);
                mma16816(c, ql4, &bH4[2 * f]);
            }
        }
    }

    // ---- epilogue ----
#pragma unroll
    for (int nb = 0; nb < 8; nb++) {
        const int e0 = nb * 8 + 2 * t4;
        const int i0 = i0w + gid;
        *(float2*)(og + base + (size_t)i0 * ROWSTRIDE + e0) =
            make_float2(oacc[nb][0], oacc[nb][1]);
        *(float2*)(og + base + (size_t)(i0 + 8) * ROWSTRIDE + e0) =
            make_float2(oacc[nb][2], oacc[nb][3]);
    }
}

// ---------------------------------------------------------------------------
// kernel_launch
// ---------------------------------------------------------------------------
extern "C" void kernel_launch(void* const* d_in, const int* in_sizes, int n_in,
                              void* d_out, int out_size) {
    (void)in_sizes; (void)n_in; (void)out_size;
    const float* q = (const float*)d_in[0];
    const float* k = (const float*)d_in[1];
    const float* v = (const float*)d_in[2];
    float* out = (float*)d_out;

    cudaFuncSetAttribute(kv_chunk_kernel, cudaFuncAttributeMaxDynamicSharedMemorySize,
                         KV_SMEM);
    kv_chunk_kernel<<<BH * NC, 512, KV_SMEM>>>(k, v);
    kv_prefix_kernel<<<BH * 16, 256>>>();

    cudaFuncSetAttribute(out_mma_kernel, cudaFuncAttributeMaxDynamicSharedMemorySize,
                         O_SMEM);
    out_mma_kernel<<<BH * NC, 256, O_SMEM>>>(q, k, v, out);
}

// round 8
// speedup vs baseline: 1.4656x; 1.1145x over previous
#include <cuda_runtime.h>
#include <cuda_bf16.h>
#include <cstdint>
#include <cstddef>

// Problem constants (B=4, S=4096, H=16, D=64)
#define BSZ 4
#define SEQ 4096
#define NH 16
#define HD 64
#define CK 128
#define NC 32
#define BH 64
#define ROWSTRIDE 1024

// Per-chunk KV outer products -> exclusive prefix (in place). 32 MB.
__device__ float g_kv[(size_t)BH * NC * HD * HD];

// ---------------------------------------------------------------------------
// PTX helpers (base sm_100-safe)
// ---------------------------------------------------------------------------
__device__ __forceinline__ uint32_t smem_u32(const void* p) {
    uint32_t a;
    asm("{ .reg .u64 t; cvta.to.shared.u64 t, %1; cvt.u32.u64 %0, t; }"
        : "=r"(a) : "l"(p));
    return a;
}
__device__ __forceinline__ void ldm4(uint32_t* r, uint32_t addr) {
    asm volatile("ldmatrix.sync.aligned.m8n8.x4.shared.b16 {%0,%1,%2,%3}, [%4];"
                 : "=r"(r[0]), "=r"(r[1]), "=r"(r[2]), "=r"(r[3]) : "r"(addr));
}
__device__ __forceinline__ void ldm4t(uint32_t* r, uint32_t addr) {
    asm volatile("ldmatrix.sync.aligned.m8n8.x4.trans.shared.b16 {%0,%1,%2,%3}, [%4];"
                 : "=r"(r[0]), "=r"(r[1]), "=r"(r[2]), "=r"(r[3]) : "r"(addr));
}
__device__ __forceinline__ void mma16816(float* c, const uint32_t* a, const uint32_t* b) {
    asm volatile(
        "mma.sync.aligned.m16n8k16.row.col.f32.bf16.bf16.f32 "
        "{%0,%1,%2,%3}, {%4,%5,%6,%7}, {%8,%9}, {%0,%1,%2,%3};"
        : "+f"(c[0]), "+f"(c[1]), "+f"(c[2]), "+f"(c[3])
        : "r"(a[0]), "r"(a[1]), "r"(a[2]), "r"(a[3]), "r"(b[0]), "r"(b[1]));
}

// swizzle for 128B rows ([*][64] bf16)
__device__ __forceinline__ uint32_t sw128(uint32_t x) { return x ^ ((x >> 3) & 0x70); }

// split fp32 -> (hi, lo) bf16
__device__ __forceinline__ void split1(float x, __nv_bfloat16& h, __nv_bfloat16& l) {
    h = __float2bfloat16(x);
    l = __float2bfloat16(x - __bfloat162float(h));
}
__device__ __forceinline__ void split2(float x0, float x1, uint32_t& hi, uint32_t& lo) {
    __nv_bfloat16 h0, l0, h1, l1;
    split1(x0, h0, l0);
    split1(x1, h1, l1);
    hi = (uint32_t)__bfloat16_as_ushort(h0) | ((uint32_t)__bfloat16_as_ushort(h1) << 16);
    lo = (uint32_t)__bfloat16_as_ushort(l0) | ((uint32_t)__bfloat16_as_ushort(l1) << 16);
}

// ---------------------------------------------------------------------------
// Kernel 1: per-chunk KV_n[d][e] = sum_j k[j][d] * v[j][e]   (unchanged)
// ---------------------------------------------------------------------------
#define KV_KH 0
#define KV_KL 16384
#define KV_VH 32768
#define KV_VL 49152
#define KV_SMEM 65536

__global__ __launch_bounds__(512, 2) void kv_chunk_kernel(
    const float* __restrict__ kg, const float* __restrict__ vg) {
    extern __shared__ char sm[];
    const uint32_t smb = smem_u32(sm);

    const int tid = threadIdx.x, wid = tid >> 5, lane = tid & 31;
    const int blk = blockIdx.x;
    const int n = blk & (NC - 1), bh = blk >> 5;
    const int h = bh & (NH - 1), b = bh >> 4;
    const size_t base = ((size_t)b * SEQ + (size_t)n * CK) * ROWSTRIDE + (size_t)h * HD;

#pragma unroll
    for (int p = tid; p < 4096; p += 512) {
        const int j = p >> 5, dp = p & 31;
        const size_t g = base + (size_t)j * ROWSTRIDE + 2 * dp;
        float2 xk = *(const float2*)(kg + g);
        float2 xv = *(const float2*)(vg + g);
        uint32_t kh, kl, vh, vl;
        split2(xk.x, xk.y, kh, kl);
        split2(xv.x, xv.y, vh, vl);
        const uint32_t off = sw128((uint32_t)(j * 128 + dp * 4));
        *(uint32_t*)(sm + KV_KH + off) = kh;
        *(uint32_t*)(sm + KV_KL + off) = kl;
        *(uint32_t*)(sm + KV_VH + off) = vh;
        *(uint32_t*)(sm + KV_VL + off) = vl;
    }
    __syncthreads();

    const int wy = wid >> 2;          // d block of 16
    const int wx = wid & 3;           // e block of 16
    const int la7 = lane & 7;

    float acc[2][4];
#pragma unroll
    for (int f = 0; f < 2; f++)
#pragma unroll
        for (int c = 0; c < 4; c++) acc[f][c] = 0.f;

#pragma unroll 2
    for (int kb = 0; kb < 8; kb++) {
        const int k0 = kb * 16;
        uint32_t aH[4], aL[4];
        {
            const int row = k0 + ((lane >> 4) << 3) + la7;
            const int col = wy * 16 + ((lane >> 3) & 1) * 8;
            const uint32_t off = sw128((uint32_t)(row * 128 + col * 2));
            ldm4t(aH, smb + KV_KH + off);
            ldm4t(aL, smb + KV_KL + off);
        }
        uint32_t bH[4], bL[4];
        {
            const int row = k0 + ((lane >> 3) & 1) * 8 + la7;
            const int col = wx * 16 + ((lane >> 4) << 3);
            const uint32_t off = sw128((uint32_t)(row * 128 + col * 2));
            ldm4t(bH, smb + KV_VH + off);
            ldm4t(bL, smb + KV_VL + off);
        }
#pragma unroll
        for (int f = 0; f < 2; f++) {
            float* c = acc[f];
            mma16816(c, aH, &bH[2 * f]);
            mma16816(c, aH, &bL[2 * f]);
            mma16816(c, aL, &bH[2 * f]);
        }
    }

    {
        float* out = g_kv + ((size_t)bh * NC + n) * (HD * HD);
        const int gid = lane >> 2, t4 = lane & 3;
#pragma unroll
        for (int f = 0; f < 2; f++) {
            const int e0 = wx * 16 + f * 8 + 2 * t4;
            const int d0 = wy * 16 + gid;
            *(float2*)(out + d0 * HD + e0) = make_float2(acc[f][0], acc[f][1]);
            *(float2*)(out + (d0 + 8) * HD + e0) = make_float2(acc[f][2], acc[f][3]);
        }
    }
}

// ---------------------------------------------------------------------------
// Kernel 2: in-place exclusive prefix over chunk axis (unchanged)
// ---------------------------------------------------------------------------
__global__ __launch_bounds__(256, 1) void kv_prefix_kernel() {
    const int bh  = blockIdx.x >> 4;
    const int off = ((blockIdx.x & 15) << 8) + threadIdx.x;
    float* p = g_kv + (size_t)bh * NC * (HD * HD) + off;
    float run = 0.f;
#pragma unroll
    for (int n = 0; n < NC; n++) {
        const float t = p[(size_t)n * (HD * HD)];
        p[(size_t)n * (HD * HD)] = run;
        run += t;
    }
}

// ---------------------------------------------------------------------------
// Kernel 3: out kernel, strip-mined register-resident S, 256 thr, 112 KB,
// 2 CTAs/SM.
//   O = tril(Q K^T) V + Q KV_prev  per 128-row chunk.
// smem: QH 0, QL 16K       ([128][64] K-major, SW128)
//       KH 32K, KL 48K     ([128][64] K-major, SW128)
//       VH 64K, VL 80K     ([128][64] natural [j][e], SW128)
//       KVH 96K, KVL 104K  ([64][64] natural [d][e], SW128)
// 8 warps, each owns 16 i-rows (i0w = wid*16), all 64 e-cols.
// Q A-fragments loaded ONCE (32 regs, resident). Then per 16-wide j-strip
// (js = 0..wid, exact causal triangle): S strip (8 regs) -> mask+split in
// registers -> one A-frag pair -> immediately consumed against V. Finally
// O += Q KV_prev using the same resident Q frags.
// ---------------------------------------------------------------------------
#define O_QH 0
#define O_QL 16384
#define O_KH 32768
#define O_KL 49152
#define O_VH 65536
#define O_VL 81920
#define O_KVH 98304
#define O_KVL 106496
#define O_SMEM 114688

__global__ __launch_bounds__(256, 2) void out_mma_kernel(
    const float* __restrict__ qg, const float* __restrict__ kg,
    const float* __restrict__ vg, float* __restrict__ og) {
    extern __shared__ char sm[];
    const uint32_t smb = smem_u32(sm);

    const int tid = threadIdx.x, wid = tid >> 5, lane = tid & 31;
    const int blk = blockIdx.x;
    const int n = blk & (NC - 1), bh = blk >> 5;
    const int h = bh & (NH - 1), b = bh >> 4;
    const size_t base = ((size_t)b * SEQ + (size_t)n * CK) * ROWSTRIDE + (size_t)h * HD;

    // ---- load + split: Q, K, V ----
#pragma unroll
    for (int p = tid; p < 4096; p += 256) {
        const int i = p >> 5, dp = p & 31;
        const size_t g = base + (size_t)i * ROWSTRIDE + 2 * dp;
        float2 xq = *(const float2*)(qg + g);
        float2 xk = *(const float2*)(kg + g);
        float2 xv = *(const float2*)(vg + g);
        uint32_t hh, ll;
        const uint32_t off = sw128((uint32_t)(i * 128 + dp * 4));
        split2(xq.x, xq.y, hh, ll);
        *(uint32_t*)(sm + O_QH + off) = hh;
        *(uint32_t*)(sm + O_QL + off) = ll;
        split2(xk.x, xk.y, hh, ll);
        *(uint32_t*)(sm + O_KH + off) = hh;
        *(uint32_t*)(sm + O_KL + off) = ll;
        split2(xv.x, xv.y, hh, ll);
        *(uint32_t*)(sm + O_VH + off) = hh;
        *(uint32_t*)(sm + O_VL + off) = ll;
    }
    // KV_prev [64][64]
    {
        const float* kvsrc = g_kv + ((size_t)bh * NC + n) * (HD * HD);
#pragma unroll
        for (int p = tid; p < 2048; p += 256) {
            const int d = p >> 5, ep = p & 31;
            float2 x = *(const float2*)(kvsrc + d * 64 + 2 * ep);
            uint32_t hh, ll;
            split2(x.x, x.y, hh, ll);
            const uint32_t off = sw128((uint32_t)(d * 128 + ep * 4));
            *(uint32_t*)(sm + O_KVH + off) = hh;
            *(uint32_t*)(sm + O_KVL + off) = ll;
        }
    }
    __syncthreads();

    const int i0w = wid * 16;            // warp's first i-row
    const int la7 = lane & 7;
    const int la15 = lane & 15;
    const int gid = lane >> 2, t4 = lane & 3;

    // ---- resident Q A-fragments (loaded once) ----
    uint32_t aQH[4][4], aQL[4][4];
#pragma unroll
    for (int kb = 0; kb < 4; kb++) {
        const int row = i0w + la15;
        const int col = kb * 16 + ((lane >> 4) << 3);
        const uint32_t off = sw128((uint32_t)(row * 128 + col * 2));
        ldm4(aQH[kb], smb + O_QH + off);
        ldm4(aQL[kb], smb + O_QL + off);
    }

    float oacc[8][4];                    // e n-blocks 0..7 (e = 8nb..)
#pragma unroll
    for (int nb = 0; nb < 8; nb++)
#pragma unroll
        for (int c = 0; c < 4; c++) oacc[nb][c] = 0.f;

    // ---- causal strips: S strip (regs) -> split -> S·V ----
    for (int js = 0; js <= wid; js++) {
        const int j0 = js * 16;

        // S strip = Q K^T, j in [j0, j0+16)
        float sacc[2][4];
#pragma unroll
        for (int f = 0; f < 2; f++)
#pragma unroll
            for (int c = 0; c < 4; c++) sacc[f][c] = 0.f;

#pragma unroll
        for (int kb = 0; kb < 4; kb++) {
            uint32_t bH4[4], bL4[4];
            const int row = j0 + ((lane >> 4) << 3) + la7;
            const int col = kb * 16 + ((lane >> 3) & 1) * 8;
            const uint32_t off = sw128((uint32_t)(row * 128 + col * 2));
            ldm4(bH4, smb + O_KH + off);
            ldm4(bL4, smb + O_KL + off);
#pragma unroll
            for (int f = 0; f < 2; f++) {
                float* c = sacc[f];
                mma16816(c, aQH[kb], &bH4[2 * f]);
                mma16816(c, aQH[kb], &bL4[2 * f]);
                mma16816(c, aQL[kb], &bH4[2 * f]);
            }
        }

        // mask + split in registers -> one A-frag pair (k=16)
        uint32_t aSH[4], aSL[4];
#pragma unroll
        for (int nb = 0; nb < 2; nb++) {
            const int jj = j0 + nb * 8 + 2 * t4;
            const int iLo = i0w + gid, iHi = iLo + 8;
            const float x0 = (jj     <= iLo) ? sacc[nb][0] : 0.f;
            const float x1 = (jj + 1 <= iLo) ? sacc[nb][1] : 0.f;
            const float x2 = (jj     <= iHi) ? sacc[nb][2] : 0.f;
            const float x3 = (jj + 1 <= iHi) ? sacc[nb][3] : 0.f;
            uint32_t hi01, lo01, hi23, lo23;
            split2(x0, x1, hi01, lo01);
            split2(x2, x3, hi23, lo23);
            aSH[nb * 2] = hi01;  aSH[nb * 2 + 1] = hi23;
            aSL[nb * 2] = lo01;  aSL[nb * 2 + 1] = lo23;
        }

        // S·V for this strip (B = V rows [j0, j0+16), trans)
        {
            const int rowv = j0 + ((lane >> 3) & 1) * 8 + la7;
#pragma unroll
            for (int pe = 0; pe < 4; pe++) {
                uint32_t vH4[4], vL4[4];
                const int col = pe * 16 + ((lane >> 4) << 3);
                const uint32_t off = sw128((uint32_t)(rowv * 128 + col * 2));
                ldm4t(vH4, smb + O_VH + off);
                ldm4t(vL4, smb + O_VL + off);
#pragma unroll
                for (int f = 0; f < 2; f++) {
                    float* c = oacc[pe * 2 + f];
                    mma16816(c, aSH, &vH4[2 * f]);
                    mma16816(c, aSH, &vL4[2 * f]);
                    mma16816(c, aSL, &vH4[2 * f]);
                }
            }
        }
    }

    // ---- O += Q KV_prev (resident aQ) ----
#pragma unroll
    for (int kb = 0; kb < 4; kb++) {
        const int rowkv = kb * 16 + ((lane >> 3) & 1) * 8 + la7;
#pragma unroll
        for (int pe = 0; pe < 4; pe++) {
            uint32_t bH4[4], bL4[4];
            const int col = pe * 16 + ((lane >> 4) << 3);
            const uint32_t off = sw128((uint32_t)(rowkv * 128 + col * 2));
            ldm4t(bH4, smb + O_KVH + off);
            ldm4t(bL4, smb + O_KVL + off);
#pragma unroll
            for (int f = 0; f < 2; f++) {
                float* c = oacc[pe * 2 + f];
                mma16816(c, aQH[kb], &bH4[2 * f]);
                mma16816(c, aQH[kb], &bL4[2 * f]);
                mma16816(c, aQL[kb], &bH4[2 * f]);
            }
        }
    }

    // ---- epilogue ----
#pragma unroll
    for (int nb = 0; nb < 8; nb++) {
        const int e0 = nb * 8 + 2 * t4;
        const int i0 = i0w + gid;
        *(float2*)(og + base + (size_t)i0 * ROWSTRIDE + e0) =
            make_float2(oacc[nb][0], oacc[nb][1]);
        *(float2*)(og + base + (size_t)(i0 + 8) * ROWSTRIDE + e0) =
            make_float2(oacc[nb][2], oacc[nb][3]);
    }
}

// ---------------------------------------------------------------------------
// kernel_launch
// ---------------------------------------------------------------------------
extern "C" void kernel_launch(void* const* d_in, const int* in_sizes, int n_in,
                              void* d_out, int out_size) {
    (void)in_sizes; (void)n_in; (void)out_size;
    const float* q = (const float*)d_in[0];
    const float* k = (const float*)d_in[1];
    const float* v = (const float*)d_in[2];
    float* out = (float*)d_out;

    cudaFuncSetAttribute(kv_chunk_kernel, cudaFuncAttributeMaxDynamicSharedMemorySize,
                         KV_SMEM);
    kv_chunk_kernel<<<BH * NC, 512, KV_SMEM>>>(k, v);
    kv_prefix_kernel<<<BH * 16, 256>>>();

    cudaFuncSetAttribute(out_mma_kernel, cudaFuncAttributeMaxDynamicSharedMemorySize,
                         O_SMEM);
    out_mma_kernel<<<BH * NC, 256, O_SMEM>>>(q, k, v, out);
}